// round 8
// baseline (speedup 1.0000x reference)
#include <cuda_runtime.h>
#include <cuda_bf16.h>
#include <float.h>

#define BZ    64
#define SEQ   2048
#define DIM   2048
#define NE    16
#define RK    4
#define SCH   16                // seq chunks for stage A
#define SPER  (SEQ / SCH)       // 128 rows per block
#define DCHB  4                 // DIM chunks for stage B
#define BLANES (DIM / DCHB / 4) // 128 float4 lanes per stageB block
#define NBLKB (BZ * DCHB)       // 256 stageB blocks

// Partial logits. Summed in fixed order by the finalizer (deterministic).
__device__ float g_p1[SCH * BZ * NE];   // from stage A (pre-mean)
__device__ float g_l2[DCHB * BZ * NE];  // from stage B slices
__device__ int   g_count;               // zero-init; reset each run by last block

// ---------------------------------------------------------------------------
// Stage A: verbatim R2 structure. 1024 blocks x 512 threads, each streams 128
// fully-contiguous 8KB rows, then a lean W_b-dot epilogue (L2-resident).
// ---------------------------------------------------------------------------
__global__ __launch_bounds__(512) void stageA_reduce(const float* __restrict__ x,
                                                     const float* __restrict__ W_b) {
    const int b    = blockIdx.x;
    const int sc   = blockIdx.y;
    const int t    = threadIdx.x;      // 0..511
    const int lane = t & 31;
    const int warp = t >> 5;           // 16 warps

    const float4* __restrict__ xp =
        reinterpret_cast<const float4*>(x)
        + ((size_t)b * SEQ + (size_t)sc * SPER) * (DIM / 4) + t;

    float4 a0 = make_float4(0.f, 0.f, 0.f, 0.f);
    float4 a1 = a0, a2 = a0, a3 = a0;

    #pragma unroll 4
    for (int s = 0; s < SPER; s += 4) {
        float4 v0 = xp[(size_t)(s + 0) * (DIM / 4)];
        float4 v1 = xp[(size_t)(s + 1) * (DIM / 4)];
        float4 v2 = xp[(size_t)(s + 2) * (DIM / 4)];
        float4 v3 = xp[(size_t)(s + 3) * (DIM / 4)];
        a0.x += v0.x; a0.y += v0.y; a0.z += v0.z; a0.w += v0.w;
        a1.x += v1.x; a1.y += v1.y; a1.z += v1.z; a1.w += v1.w;
        a2.x += v2.x; a2.y += v2.y; a2.z += v2.z; a2.w += v2.w;
        a3.x += v3.x; a3.y += v3.y; a3.z += v3.z; a3.w += v3.w;
    }
    float4 r;
    r.x = (a0.x + a1.x) + (a2.x + a3.x);
    r.y = (a0.y + a1.y) + (a2.y + a3.y);
    r.z = (a0.z + a1.z) + (a2.z + a3.z);
    r.w = (a0.w + a1.w) + (a2.w + a3.w);

    const float4* __restrict__ wb4 = reinterpret_cast<const float4*>(W_b);
    float p[NE];
    #pragma unroll
    for (int e = 0; e < NE; e++) {
        float4 w = wb4[(size_t)e * (DIM / 4) + t];
        p[e] = (r.x * w.x + r.y * w.y) + (r.z * w.z + r.w * w.w);
    }

    #pragma unroll
    for (int e = 0; e < NE; e++) {
        #pragma unroll
        for (int off = 16; off > 0; off >>= 1)
            p[e] += __shfl_down_sync(0xFFFFFFFFu, p[e], off);
    }

    __shared__ float s_red[16][NE];
    if (lane == 0) {
        #pragma unroll
        for (int e = 0; e < NE; e++) s_red[warp][e] = p[e];
    }
    __syncthreads();

    if (t < NE) {
        float v = 0.f;
        #pragma unroll
        for (int w = 0; w < 16; w++) v += s_red[w][t];
        g_p1[((size_t)sc * BZ + b) * NE + t] = v;
    }
}

// ---------------------------------------------------------------------------
// Stage B: grid (BZ, DCHB) x 128 threads. Each block: embed-mean dot W_c on a
// 512-dim slice -> g_l2. Last block (ticket) runs the 64-row finalize inline.
// ---------------------------------------------------------------------------
__global__ __launch_bounds__(128) void stageB_finalize(
    const int*   __restrict__ idx,
    const float* __restrict__ embed,
    const float* __restrict__ W_c,
    float*       __restrict__ out,
    int out_size)
{
    const int b    = blockIdx.x;
    const int dc   = blockIdx.y;
    const int t    = threadIdx.x;      // 0..127 = one float4 lane each
    const int lane = t & 31;
    const int warp = t >> 5;           // 4 warps

    const int base4 = dc * BLANES + t; // float4 index into a row

    const int i0 = idx[b * RK + 0];
    const int i1 = idx[b * RK + 1];
    const int i2 = idx[b * RK + 2];
    const int i3 = idx[b * RK + 3];

    const float4* __restrict__ em4 = reinterpret_cast<const float4*>(embed);
    const float4* __restrict__ wc4 = reinterpret_cast<const float4*>(W_c);

    float4 e0 = em4[(size_t)i0 * (DIM / 4) + base4];
    float4 e1 = em4[(size_t)i1 * (DIM / 4) + base4];
    float4 e2 = em4[(size_t)i2 * (DIM / 4) + base4];
    float4 e3 = em4[(size_t)i3 * (DIM / 4) + base4];
    float4 h;
    h.x = 0.25f * ((e0.x + e1.x) + (e2.x + e3.x));
    h.y = 0.25f * ((e0.y + e1.y) + (e2.y + e3.y));
    h.z = 0.25f * ((e0.z + e1.z) + (e2.z + e3.z));
    h.w = 0.25f * ((e0.w + e1.w) + (e2.w + e3.w));

    float p[NE];
    #pragma unroll
    for (int e = 0; e < NE; e++) {
        float4 w = wc4[(size_t)e * (DIM / 4) + base4];
        p[e] = (h.x * w.x + h.y * w.y) + (h.z * w.z + h.w * w.w);
    }

    #pragma unroll
    for (int e = 0; e < NE; e++) {
        #pragma unroll
        for (int off = 16; off > 0; off >>= 1)
            p[e] += __shfl_down_sync(0xFFFFFFFFu, p[e], off);
    }

    __shared__ float s_red[4][NE];
    __shared__ int   s_amLast;
    if (lane == 0) {
        #pragma unroll
        for (int e = 0; e < NE; e++) s_red[warp][e] = p[e];
    }
    __syncthreads();

    if (t < NE) {
        g_l2[((size_t)dc * BZ + b) * NE + t] =
            (s_red[0][t] + s_red[1][t]) + (s_red[2][t] + s_red[3][t]);
        __threadfence();
    }
    __syncthreads();

    if (t == 0) {
        int ticket = atomicAdd(&g_count, 1);
        s_amLast = (ticket == NBLKB - 1);
    }
    __syncthreads();
    if (!s_amLast) return;
    __threadfence();  // acquire: see all blocks' g_l2 writes

    // ---- finalize: one thread per batch row (t<64) ----
    if (t < BZ) {
        const int bb = t;
        float l1[NE], l2[NE];
        #pragma unroll
        for (int e = 0; e < NE; e++) {
            float v1 = 0.f;
            #pragma unroll
            for (int s = 0; s < SCH; s++)
                v1 += g_p1[((size_t)s * BZ + bb) * NE + e];
            l1[e] = v1 * (1.0f / (float)SEQ);
            float v2 = 0.f;
            #pragma unroll
            for (int d = 0; d < DCHB; d++)
                v2 += g_l2[((size_t)d * BZ + bb) * NE + e];
            l2[e] = v2;
        }

        float m1 = -FLT_MAX, m2 = -FLT_MAX;
        #pragma unroll
        for (int e = 0; e < NE; e++) { m1 = fmaxf(m1, l1[e]); m2 = fmaxf(m2, l2[e]); }
        float z1 = 0.f, z2 = 0.f;
        float sm1[NE], sm2[NE];
        #pragma unroll
        for (int e = 0; e < NE; e++) {
            sm1[e] = __expf(l1[e] - m1); z1 += sm1[e];
            sm2[e] = __expf(l2[e] - m2); z2 += sm2[e];
        }
        const float iz1 = 1.f / z1, iz2 = 1.f / z2;
        float logits[NE], score[NE];
        float mC = -FLT_MAX;
        #pragma unroll
        for (int e = 0; e < NE; e++) {
            logits[e] = sm1[e] * iz1 + sm2[e] * iz2;   // IFS_WEIGHT = 1.0
            mC = fmaxf(mC, logits[e]);
        }

        // top-4: strict > keeps lowest index on ties; descending order
        int  topk[RK];
        bool taken[NE];
        #pragma unroll
        for (int e = 0; e < NE; e++) taken[e] = false;
        #pragma unroll
        for (int r2 = 0; r2 < RK; r2++) {
            float best = -FLT_MAX;
            int   bi   = 0;
            #pragma unroll
            for (int e = 0; e < NE; e++)
                if (!taken[e] && logits[e] > best) { best = logits[e]; bi = e; }
            taken[bi] = true;
            topk[r2] = bi;
        }

        float zC = 0.f;
        #pragma unroll
        for (int e = 0; e < NE; e++) { score[e] = __expf(logits[e] - mC); zC += score[e]; }
        const float izC = 1.f / zC;
        float denom = 0.f;
        #pragma unroll
        for (int e = 0; e < NE; e++) {
            score[e] *= izC;
            if (taken[e]) denom += score[e];
        }
        denom = fmaxf(denom, FLT_EPSILON);
        const float inv_d = 1.f / denom;

        if (out_size >= BZ * NE) {
            #pragma unroll
            for (int e = 0; e < NE; e++)
                out[bb * NE + e] = taken[e] ? score[e] * inv_d : 0.f;
        }
        if (out_size >= BZ * NE + BZ * RK) {
            #pragma unroll
            for (int r2 = 0; r2 < RK; r2++)
                out[BZ * NE + bb * RK + r2] = (float)topk[r2];
        }
    }
    __syncthreads();
    if (t == 0) g_count = 0;   // reset for next graph replay
}

extern "C" void kernel_launch(void* const* d_in, const int* in_sizes, int n_in,
                              void* d_out, int out_size) {
    const float* x     = (const float*)d_in[0];
    const int*   idx   = (const int*)  d_in[1];
    const float* W_b   = (const float*)d_in[2];
    const float* embed = (const float*)d_in[3];
    const float* W_c   = (const float*)d_in[4];
    float* out = (float*)d_out;

    dim3 gA(BZ, SCH);
    stageA_reduce<<<gA, 512>>>(x, W_b);
    dim3 gB(BZ, DCHB);
    stageB_finalize<<<gB, 128>>>(idx, embed, W_c, out, out_size);
}

// round 9
// speedup vs baseline: 1.1034x; 1.1034x over previous
#include <cuda_runtime.h>
#include <cuda_bf16.h>
#include <float.h>

#define BZ    64
#define SEQ   2048
#define DIM   2048
#define NE    16
#define RK    4
#define RPC   64                     // rows per stream chunk
#define NSC   (SEQ / RPC)            // 32 chunks per batch row
#define N_EMBED   BZ                 // embed tasks: ids [0, 64)
#define N_STREAM  (BZ * NSC)         // stream tasks: ids [64, 2112)
#define N_TASKS   (N_EMBED + N_STREAM)
#define NBLK  296                    // 2 blocks/SM x 148 SMs = one resident wave
#define TPB   512
#define NWARP (TPB / 32)

// Atomic-accumulated logits (zero-initialized; last block re-zeros each run).
__device__ float g_l1[BZ * NE];      // x-sum . W_b  (pre-mean)
__device__ float g_l2[BZ * NE];      // embed-mean . W_c
__device__ int   g_next;             // task counter
__device__ int   g_done;             // block-exit counter

__global__ __launch_bounds__(TPB, 2) void persistent_selector(
    const float* __restrict__ x,
    const int*   __restrict__ idx,
    const float* __restrict__ W_b,
    const float* __restrict__ embed,
    const float* __restrict__ W_c,
    float*       __restrict__ out,
    int out_size)
{
    const int t    = threadIdx.x;    // 0..511 = float4 lane over full DIM
    const int lane = t & 31;
    const int warp = t >> 5;

    __shared__ int   s_id;
    __shared__ float s_red[NWARP][NE];
    __shared__ int   s_last;

    const float4* __restrict__ x4  = reinterpret_cast<const float4*>(x);
    const float4* __restrict__ wb4 = reinterpret_cast<const float4*>(W_b);
    const float4* __restrict__ em4 = reinterpret_cast<const float4*>(embed);
    const float4* __restrict__ wc4 = reinterpret_cast<const float4*>(W_c);

    for (;;) {
        __syncthreads();                       // protect s_id / s_red reuse
        if (t == 0) s_id = atomicAdd(&g_next, 1);
        __syncthreads();
        const int id = s_id;
        if (id >= N_TASKS) break;

        float p[NE];

        if (id >= N_EMBED) {
            // ---- stream chunk: 64 contiguous rows of batch b ----
            const int c  = id - N_EMBED;
            const int b  = c >> 5;             // NSC = 32
            const int sc = c & 31;

            const float4* __restrict__ xp =
                x4 + ((size_t)b * SEQ + (size_t)sc * RPC) * (DIM / 4) + t;

            float4 a0 = make_float4(0.f, 0.f, 0.f, 0.f);
            float4 a1 = a0, a2 = a0, a3 = a0;
            #pragma unroll 4
            for (int s = 0; s < RPC; s += 4) {
                float4 v0 = xp[(size_t)(s + 0) * (DIM / 4)];
                float4 v1 = xp[(size_t)(s + 1) * (DIM / 4)];
                float4 v2 = xp[(size_t)(s + 2) * (DIM / 4)];
                float4 v3 = xp[(size_t)(s + 3) * (DIM / 4)];
                a0.x += v0.x; a0.y += v0.y; a0.z += v0.z; a0.w += v0.w;
                a1.x += v1.x; a1.y += v1.y; a1.z += v1.z; a1.w += v1.w;
                a2.x += v2.x; a2.y += v2.y; a2.z += v2.z; a2.w += v2.w;
                a3.x += v3.x; a3.y += v3.y; a3.z += v3.z; a3.w += v3.w;
            }
            float4 r;
            r.x = (a0.x + a1.x) + (a2.x + a3.x);
            r.y = (a0.y + a1.y) + (a2.y + a3.y);
            r.z = (a0.z + a1.z) + (a2.z + a3.z);
            r.w = (a0.w + a1.w) + (a2.w + a3.w);

            #pragma unroll
            for (int e = 0; e < NE; e++) {
                float4 w = wb4[(size_t)e * (DIM / 4) + t];
                p[e] = (r.x * w.x + r.y * w.y) + (r.z * w.z + r.w * w.w);
            }
            #pragma unroll
            for (int e = 0; e < NE; e++) {
                #pragma unroll
                for (int off = 16; off > 0; off >>= 1)
                    p[e] += __shfl_down_sync(0xFFFFFFFFu, p[e], off);
            }
            if (lane == 0) {
                #pragma unroll
                for (int e = 0; e < NE; e++) s_red[warp][e] = p[e];
            }
            __syncthreads();
            if (t < NE) {
                float v = 0.f;
                #pragma unroll
                for (int w = 0; w < NWARP; w++) v += s_red[w][t];
                atomicAdd(&g_l1[b * NE + t], v);
            }
        } else {
            // ---- embed task: embed-mean . W_c for batch row id ----
            const int b  = id;
            const int i0 = idx[b * RK + 0];
            const int i1 = idx[b * RK + 1];
            const int i2 = idx[b * RK + 2];
            const int i3 = idx[b * RK + 3];
            float4 e0 = em4[(size_t)i0 * (DIM / 4) + t];
            float4 e1 = em4[(size_t)i1 * (DIM / 4) + t];
            float4 e2 = em4[(size_t)i2 * (DIM / 4) + t];
            float4 e3 = em4[(size_t)i3 * (DIM / 4) + t];
            float4 h;
            h.x = 0.25f * ((e0.x + e1.x) + (e2.x + e3.x));
            h.y = 0.25f * ((e0.y + e1.y) + (e2.y + e3.y));
            h.z = 0.25f * ((e0.z + e1.z) + (e2.z + e3.z));
            h.w = 0.25f * ((e0.w + e1.w) + (e2.w + e3.w));
            #pragma unroll
            for (int e = 0; e < NE; e++) {
                float4 w = wc4[(size_t)e * (DIM / 4) + t];
                p[e] = (h.x * w.x + h.y * w.y) + (h.z * w.z + h.w * w.w);
            }
            #pragma unroll
            for (int e = 0; e < NE; e++) {
                #pragma unroll
                for (int off = 16; off > 0; off >>= 1)
                    p[e] += __shfl_down_sync(0xFFFFFFFFu, p[e], off);
            }
            if (lane == 0) {
                #pragma unroll
                for (int e = 0; e < NE; e++) s_red[warp][e] = p[e];
            }
            __syncthreads();
            if (t < NE) {
                float v = 0.f;
                #pragma unroll
                for (int w = 0; w < NWARP; w++) v += s_red[w][t];
                atomicAdd(&g_l2[b * NE + t], v);
            }
        }
    }

    // ---- block exit: last block finalizes ----
    __threadfence();
    __syncthreads();
    if (t == 0) s_last = (atomicAdd(&g_done, 1) == NBLK - 1);
    __syncthreads();
    if (!s_last) return;
    __threadfence();   // acquire: all blocks' atomics visible

    if (t < BZ) {
        const int bb = t;
        float l1[NE], l2[NE];
        #pragma unroll
        for (int e = 0; e < NE; e++) {
            l1[e] = g_l1[bb * NE + e] * (1.0f / (float)SEQ);
            l2[e] = g_l2[bb * NE + e];
        }

        float m1 = -FLT_MAX, m2 = -FLT_MAX;
        #pragma unroll
        for (int e = 0; e < NE; e++) { m1 = fmaxf(m1, l1[e]); m2 = fmaxf(m2, l2[e]); }
        float z1 = 0.f, z2 = 0.f;
        float sm1[NE], sm2[NE];
        #pragma unroll
        for (int e = 0; e < NE; e++) {
            sm1[e] = __expf(l1[e] - m1); z1 += sm1[e];
            sm2[e] = __expf(l2[e] - m2); z2 += sm2[e];
        }
        const float iz1 = 1.f / z1, iz2 = 1.f / z2;
        float logits[NE], score[NE];
        float mC = -FLT_MAX;
        #pragma unroll
        for (int e = 0; e < NE; e++) {
            logits[e] = sm1[e] * iz1 + sm2[e] * iz2;   // IFS_WEIGHT = 1.0
            mC = fmaxf(mC, logits[e]);
        }

        // top-4: strict > keeps lowest index on ties; descending order
        int  topk[RK];
        bool taken[NE];
        #pragma unroll
        for (int e = 0; e < NE; e++) taken[e] = false;
        #pragma unroll
        for (int r2 = 0; r2 < RK; r2++) {
            float best = -FLT_MAX;
            int   bi   = 0;
            #pragma unroll
            for (int e = 0; e < NE; e++)
                if (!taken[e] && logits[e] > best) { best = logits[e]; bi = e; }
            taken[bi] = true;
            topk[r2] = bi;
        }

        float zC = 0.f;
        #pragma unroll
        for (int e = 0; e < NE; e++) { score[e] = __expf(logits[e] - mC); zC += score[e]; }
        const float izC = 1.f / zC;
        float denom = 0.f;
        #pragma unroll
        for (int e = 0; e < NE; e++) {
            score[e] *= izC;
            if (taken[e]) denom += score[e];
        }
        denom = fmaxf(denom, FLT_EPSILON);
        const float inv_d = 1.f / denom;

        if (out_size >= BZ * NE) {
            #pragma unroll
            for (int e = 0; e < NE; e++)
                out[bb * NE + e] = taken[e] ? score[e] * inv_d : 0.f;
        }
        if (out_size >= BZ * NE + BZ * RK) {
            #pragma unroll
            for (int r2 = 0; r2 < RK; r2++)
                out[BZ * NE + bb * RK + r2] = (float)topk[r2];
        }
    }
    __syncthreads();   // finalize reads complete before state reset

    // reset state for next graph replay
    if (t == 0) { g_next = 0; g_done = 0; }
    for (int i = t; i < BZ * NE; i += TPB) { g_l1[i] = 0.f; g_l2[i] = 0.f; }
}

extern "C" void kernel_launch(void* const* d_in, const int* in_sizes, int n_in,
                              void* d_out, int out_size) {
    const float* x     = (const float*)d_in[0];
    const int*   idx   = (const int*)  d_in[1];
    const float* W_b   = (const float*)d_in[2];
    const float* embed = (const float*)d_in[3];
    const float* W_c   = (const float*)d_in[4];
    float* out = (float*)d_out;

    persistent_selector<<<NBLK, TPB>>>(x, idx, W_b, embed, W_c, out, out_size);
}